// round 12
// baseline (speedup 1.0000x reference)
#include <cuda_runtime.h>
#include <cstdint>
#include <cstddef>

#define N_MAX 50000
#define E_MAX 500000

// ---------------- scratch ----------------
__device__ float g_PQ[(size_t)N_MAX * 256];
__device__ float g_edge_m[(size_t)E_MAX * 128];
// permuted tf32 B matrices (fragment-segment layout, see bperm_idx)
__device__ float g_B1p[2 * 16896];   // two 128-row halves of [A1;A2]
__device__ float g_B3p[16896];
__device__ float g_edge_e[E_MAX];
__device__ float g_rel_att[E_MAX];
__device__ float g_arow[N_MAX];
__device__ float g_erow[N_MAX];
__device__ float g_ecol[N_MAX];
__device__ float g_new_rank[N_MAX];

// ---------------- init ----------------
__global__ void k_init(float* __restrict__ out, int N) {
    int i = blockIdx.x * blockDim.x + threadIdx.x;
    int total = N * 128;
    if (i < total) out[i] = 0.0f;
    if (i < N) { g_arow[i] = 0.0f; g_erow[i] = 0.0f; g_ecol[i] = 0.0f; }
}

__device__ __forceinline__ float to_tf32(float x) {
    uint32_t u;
    asm("cvt.rna.tf32.f32 %0, %1;" : "=r"(u) : "f"(x));
    return __uint_as_float(u);
}

// permuted index for B[nn][k], nn in [0,128), k in [0,128):
// chunk-major, then segment (matches MMA fragment read side)
__device__ __forceinline__ int bperm_idx(int nn, int k) {
    int chunk = k >> 5, kk = k & 31;
    int seg  = ((nn >> 6) * 8 + ((nn >> 3) & 7)) * 4 + (kk >> 3);
    int lane = (nn & 7) * 4 + (kk & 3);
    int elem = (kk >> 2) & 1;
    return chunk * 4224 + seg * 66 + lane * 2 + elem;
}

// ---------------- weight extraction + permutation (tf32-rounded) ----------------
__global__ void k_prep(const float* __restrict__ a) {
    int i = blockIdx.x * blockDim.x + threadIdx.x;
    if (i < 256 * 128) {             // B1 = [A1; A2]
        int o = i >> 7, k = i & 127;
        float v = (o < 128) ? a[o * 384 + k] : a[(o - 128) * 384 + 128 + k];
        int half = o >> 7, nn = o & 127;
        g_B1p[half * 16896 + bperm_idx(nn, k)] = to_tf32(v);
    }
    if (i < 128 * 128) {             // B3
        int o = i >> 7, k = i & 127;
        g_B3p[bperm_idx(o, k)] = to_tf32(a[o * 384 + 256 + k]);
    }
}

__device__ __forceinline__ float lrelu(float x) { return (x > 0.0f) ? x : 0.2f * x; }

// edge indices are int32 (JAX downcasts int64 without x64 enabled)
__device__ __forceinline__ void edge_src_dst(
    const int* __restrict__ edge, const int* __restrict__ nhop,
    int e, int E1, int E2, int& src, int& dst)
{
    if (e < E1) { src = edge[e]; dst = edge[E1 + e]; }
    else        { int e2 = e - E1; src = nhop[e2]; dst = nhop[E2 + e2]; }
}

__device__ __forceinline__ void mma_tf32(float* c, const uint32_t* a, const uint32_t* b) {
    asm volatile(
        "mma.sync.aligned.m16n8k8.row.col.f32.tf32.tf32.f32 "
        "{%0,%1,%2,%3}, {%4,%5,%6,%7}, {%8,%9}, {%0,%1,%2,%3};"
        : "+f"(c[0]), "+f"(c[1]), "+f"(c[2]), "+f"(c[3])
        : "r"(a[0]), "r"(a[1]), "r"(a[2]), "r"(a[3]), "r"(b[0]), "r"(b[1]));
}

__device__ __forceinline__ uint32_t smem_u32(const void* p) {
    return (uint32_t)__cvta_generic_to_shared(p);
}

// smem layout (floats): Bs_all[16896] | As[2*4224] | a2s[128] | sdot[128]
#define SMEM_FLOATS (16896 + 8448 + 128 + 128)
#define SMEM_BYTES  (SMEM_FLOATS * 4)

// ---------------- tf32 tensor-core GEMM: C[m][n] = sum_k A[m][k]*B[n][k], K=128 ----------------
// B fully resident in smem (pre-permuted, cp.async once). A double-buffered, one barrier/chunk.
__global__ __launch_bounds__(256, 2) void k_sgemm(
    const float* __restrict__ A0, const float* __restrict__ A1, int splitM,
    int M, int mode,
    const int* __restrict__ edge, const int* __restrict__ nhop,
    const float* __restrict__ a2, int E1, int E2)
{
    extern __shared__ __align__(16) float smem[];
    float* Bs_all = smem;              // 16896
    float* As     = smem + 16896;      // 2 x 4224
    float* a2s    = smem + 25344;      // 128
    float* sdot   = smem + 25472;      // 128

    const float* __restrict__ Bp = (mode == 0) ? (g_B1p + blockIdx.y * 16896) : g_B3p;

    const int t     = threadIdx.x;
    const int lane  = t & 31;
    const int wid   = t >> 5;
    const int warpM = wid >> 1;   // 0..3
    const int warpN = wid & 1;    // 0..1
    const int m0    = blockIdx.x * 128;
    const int n0    = blockIdx.y * 128;

    // ---- issue B copy (linear, raw: already tf32 + permuted) ----
    for (int idx = t; idx < 4224; idx += 256) {
        asm volatile("cp.async.ca.shared.global [%0], [%1], 16;"
                     :: "r"(smem_u32(Bs_all + idx * 4)), "l"(Bp + idx * 4));
    }
    asm volatile("cp.async.commit_group;");

    if (t < 128) { sdot[t] = 0.0f; if (mode == 1) a2s[t] = a2[t]; }

    float acc[2][8][4];
#pragma unroll
    for (int i = 0; i < 2; i++)
#pragma unroll
        for (int j = 0; j < 8; j++)
#pragma unroll
            for (int c = 0; c < 4; c++) acc[i][j][c] = 0.0f;

    const int srow = t >> 3;        // 0..31
    const int scol = (t & 7) * 4;   // 0,4,...,28

    // staging decomposition (constant per thread)
    const int i_s   = srow >> 4;
    const int lane0 = (srow & 7) << 2;
    const int ks_s  = scol >> 3;
    const int cA    = ((scol >> 2) & 1) * 2 + ((srow >> 3) & 1);

    float4 pa[4];
    auto loadA = [&](int kc) {
#pragma unroll
        for (int p = 0; p < 4; ++p) {
            int m = m0 + p * 32 + srow;
            float4 v = make_float4(0.f, 0.f, 0.f, 0.f);
            if (m < M) {
                const float* arow = (m < splitM) ? (A0 + (size_t)m * 128)
                                                 : (A1 + (size_t)(m - splitM) * 128);
                v = *reinterpret_cast<const float4*>(arow + kc + scol);
            }
            pa[p] = v;
        }
    };
    auto stageA = [&](float* buf) {
#pragma unroll
        for (int p = 0; p < 4; ++p) {
            int segA = (p * 2 + i_s) * 4 + ks_s;
            float* ap = buf + segA * 132 + lane0 * 4 + cA;
            ap[0]  = to_tf32(pa[p].x);
            ap[4]  = to_tf32(pa[p].y);
            ap[8]  = to_tf32(pa[p].z);
            ap[12] = to_tf32(pa[p].w);
        }
    };

    // prologue: chunk0 staged, chunk1 in regs, B landed
    loadA(0);
    stageA(As);
    loadA(32);
    asm volatile("cp.async.wait_group 0;" ::: "memory");
    __syncthreads();

#pragma unroll
    for (int ci = 0; ci < 4; ++ci) {
        if (ci < 3) stageA(As + ((ci + 1) & 1) * 4224);  // overlap with MMAs below
        if (ci < 2) loadA((ci + 2) * 32);                // latency hidden under this chunk

        const float* Ac = As + (ci & 1) * 4224;
        const float* Bc = Bs_all + ci * 4224;
#pragma unroll
        for (int ks = 0; ks < 4; ++ks) {
            uint32_t af[2][4];
#pragma unroll
            for (int i = 0; i < 2; i++) {
                int seg = (warpM * 2 + i) * 4 + ks;
                float4 fa = reinterpret_cast<const float4*>(Ac + seg * 132)[lane];
                af[i][0] = __float_as_uint(fa.x);
                af[i][1] = __float_as_uint(fa.y);
                af[i][2] = __float_as_uint(fa.z);
                af[i][3] = __float_as_uint(fa.w);
            }
            uint32_t bf[8][2];
#pragma unroll
            for (int j = 0; j < 8; j++) {
                int seg = (warpN * 8 + j) * 4 + ks;
                float2 fb = reinterpret_cast<const float2*>(Bc + seg * 66)[lane];
                bf[j][0] = __float_as_uint(fb.x);
                bf[j][1] = __float_as_uint(fb.y);
            }
#pragma unroll
            for (int i = 0; i < 2; i++)
#pragma unroll
                for (int j = 0; j < 8; j++)
                    mma_tf32(acc[i][j], af[i], bf[j]);
        }
        __syncthreads();
    }

    if (mode == 0) {
#pragma unroll
        for (int i = 0; i < 2; i++) {
            int m = m0 + warpM * 32 + i * 16 + (lane >> 2);
#pragma unroll
            for (int j = 0; j < 8; j++) {
                int col = n0 + warpN * 64 + j * 8 + 2 * (lane & 3);
                if (m < M)
                    *reinterpret_cast<float2*>(&g_PQ[(size_t)m * 256 + col]) =
                        make_float2(acc[i][j][0], acc[i][j][1]);
                if (m + 8 < M)
                    *reinterpret_cast<float2*>(&g_PQ[(size_t)(m + 8) * 256 + col]) =
                        make_float2(acc[i][j][2], acc[i][j][3]);
            }
        }
        return;
    }

    // ---- fused edge epilogue (mode 1, n0 == 0, row = edge id) ----
#pragma unroll
    for (int i = 0; i < 2; i++) {
#pragma unroll
        for (int half = 0; half < 2; half++) {
            int rl = warpM * 32 + i * 16 + (lane >> 2) + 8 * half;
            int m = m0 + rl;
            float s = 0.0f;
            if (m < M) {
                int src, dst;
                edge_src_dst(edge, nhop, m, E1, E2, src, dst);
                const float* pbase = g_PQ + (size_t)src * 256;
                const float* qbase = g_PQ + (size_t)dst * 256 + 128;
                float* crow = g_edge_m + (size_t)m * 128;
#pragma unroll
                for (int j = 0; j < 8; j++) {
                    int col = warpN * 64 + j * 8 + 2 * (lane & 3);
                    float c0 = acc[i][j][half * 2 + 0];
                    float c1 = acc[i][j][half * 2 + 1];
                    float2 pv = *reinterpret_cast<const float2*>(pbase + col);
                    float2 qv = *reinterpret_cast<const float2*>(qbase + col);
                    float v0 = lrelu(c0 + pv.x + qv.x);
                    float v1 = lrelu(c1 + pv.y + qv.y);
                    *reinterpret_cast<float2*>(crow + col) = make_float2(v0, v1);
                    s += v0 * a2s[col] + v1 * a2s[col + 1];
                }
            }
            s += __shfl_xor_sync(0xffffffffu, s, 1);
            s += __shfl_xor_sync(0xffffffffu, s, 2);
            if ((lane & 3) == 0 && m < M) atomicAdd(&sdot[rl], s);
        }
    }
    __syncthreads();
    if (t < 128) {
        int m = m0 + t;
        if (m < M) {
            int src, dst;
            edge_src_dst(edge, nhop, m, E1, E2, src, dst);
            float ee = expf(-lrelu(sdot[t]));
            g_edge_e[m] = ee;
            atomicAdd(&g_arow[dst], ee);
        }
    }
}

// ---------------- rel_att + e_rowsum ----------------
__global__ void k_rel(const int* __restrict__ edge, const int* __restrict__ nhop,
                      int E1, int E2, int E)
{
    int e = blockIdx.x * blockDim.x + threadIdx.x;
    if (e >= E) return;
    int src, dst;
    edge_src_dst(edge, nhop, e, E1, E2, src, dst);
    float as = g_arow[dst];
    if (as == 0.0f) as = 1e-12f;
    float r = g_edge_e[e] / as;
    g_rel_att[e] = r;
    atomicAdd(&g_erow[src], r);
}

// ---------------- val + e_colsum ----------------
__global__ void k_val(const int* __restrict__ edge, const int* __restrict__ nhop,
                      const float* __restrict__ entity_rank, int E1, int E2, int E)
{
    int e = blockIdx.x * blockDim.x + threadIdx.x;
    if (e >= E) return;
    int src, dst;
    edge_src_dst(edge, nhop, e, E1, E2, src, dst);
    float es = g_erow[src];
    if (es == 0.0f) es = 1e-12f;
    float v = g_rel_att[e] * entity_rank[src] / es;
    atomicAdd(&g_ecol[dst], v);
}

// ---------------- new_rank ----------------
__global__ void k_rank(float* __restrict__ out, int N, int out_size) {
    int n = blockIdx.x * blockDim.x + threadIdx.x;
    if (n >= N) return;
    float nr = 0.15f + 0.85f * g_ecol[n];
    g_new_rank[n] = nr;
    if (out_size >= N * 128 + N) out[(size_t)N * 128 + n] = nr;
}

// ---------------- scatter with vector RED ----------------
__global__ __launch_bounds__(128) void k_scatter(
    const int* __restrict__ edge, const int* __restrict__ nhop,
    float* __restrict__ out, int E1, int E2, int E)
{
    int e = blockIdx.x * 4 + (threadIdx.x >> 5);
    if (e >= E) return;
    int lane = threadIdx.x & 31;
    int src, dst;
    edge_src_dst(edge, nhop, e, E1, E2, src, dst);
    float w = g_rel_att[e] * g_new_rank[src];
    float4 v = *reinterpret_cast<const float4*>(&g_edge_m[(size_t)e * 128 + lane * 4]);
    float* p = out + (size_t)dst * 128 + lane * 4;
    asm volatile("red.global.add.v4.f32 [%0], {%1, %2, %3, %4};"
                 :: "l"(p), "f"(w * v.x), "f"(w * v.y), "f"(w * v.z), "f"(w * v.w)
                 : "memory");
}

// ---------------- ELU ----------------
__global__ void k_elu(float* __restrict__ out, int total) {
    int i = blockIdx.x * blockDim.x + threadIdx.x;
    if (i >= total) return;
    float x = out[i];
    out[i] = (x > 0.0f) ? x : expm1f(x);
}

// ---------------- launch ----------------
extern "C" void kernel_launch(void* const* d_in, const int* in_sizes, int n_in,
                              void* d_out, int out_size) {
    const float* input       = (const float*)d_in[0];
    const int*   edge        = (const int*)d_in[1];
    const float* edge_embed  = (const float*)d_in[2];
    const int*   edge_nhop   = (const int*)d_in[3];
    const float* embed_nhop  = (const float*)d_in[4];
    const float* entity_rank = (const float*)d_in[5];
    const float* a           = (const float*)d_in[6];
    const float* a2          = (const float*)d_in[7];
    float* out = (float*)d_out;

    int N  = in_sizes[0] / 128;
    int E1 = in_sizes[1] / 2;
    int E2 = in_sizes[3] / 2;
    int E  = E1 + E2;

    cudaFuncSetAttribute(k_sgemm, cudaFuncAttributeMaxDynamicSharedMemorySize, SMEM_BYTES);

    k_init<<<(N * 128 + 255) / 256, 256>>>(out, N);
    k_prep<<<(256 * 128 + 255) / 256, 256>>>(a);

    // P|Q for all nodes
    dim3 g_pq((N + 127) / 128, 2);
    k_sgemm<<<g_pq, 256, SMEM_BYTES>>>(input, input, N, N, 0, nullptr, nullptr, nullptr, 0, 0);

    // R = emb @ A3^T fused with edge_m/edge_e/a_rowsum epilogue
    dim3 g_r((E + 127) / 128, 1);
    k_sgemm<<<g_r, 256, SMEM_BYTES>>>(edge_embed, embed_nhop, E1, E, 1, edge, edge_nhop, a2, E1, E2);

    k_rel<<<(E + 255) / 256, 256>>>(edge, edge_nhop, E1, E2, E);
    k_val<<<(E + 255) / 256, 256>>>(edge, edge_nhop, entity_rank, E1, E2, E);
    k_rank<<<(N + 255) / 256, 256>>>(out, N, out_size);
    k_scatter<<<(E + 3) / 4, 128>>>(edge, edge_nhop, out, E1, E2, E);
    k_elu<<<(N * 128 + 255) / 256, 256>>>(out, N * 128);
}

// round 13
// speedup vs baseline: 1.5998x; 1.5998x over previous
#include <cuda_runtime.h>
#include <cstdint>
#include <cstddef>

#define N_MAX 50000
#define E_MAX 500000

// ---------------- scratch ----------------
__device__ float g_PQ[(size_t)N_MAX * 256];
__device__ float g_edge_m[(size_t)E_MAX * 128];
__device__ float g_B1[256 * 128];     // tf32-pre-rounded [A1;A2], row-major K=128
__device__ float g_B3[128 * 128];     // tf32-pre-rounded A3
__device__ float g_sdot[E_MAX];
__device__ float g_edge_e[E_MAX];
__device__ float g_rel_att[E_MAX];
__device__ float g_arow[N_MAX];
__device__ float g_erow[N_MAX];
__device__ float g_ecol[N_MAX];
__device__ float g_new_rank[N_MAX];

__device__ __forceinline__ float to_tf32(float x) {
    uint32_t u;
    asm("cvt.rna.tf32.f32 %0, %1;" : "=r"(u) : "f"(x));
    return __uint_as_float(u);
}

// ---------------- init ----------------
__global__ void k_init(float* __restrict__ out, int N, int E) {
    int i = blockIdx.x * blockDim.x + threadIdx.x;
    int total = N * 128;
    if (i < total) out[i] = 0.0f;
    if (i < N) { g_arow[i] = 0.0f; g_erow[i] = 0.0f; g_ecol[i] = 0.0f; }
    if (i < E) g_sdot[i] = 0.0f;
}

// ---------------- weight extraction (tf32 pre-rounded) ----------------
__global__ void k_prep(const float* __restrict__ a) {
    int i = blockIdx.x * blockDim.x + threadIdx.x;
    if (i < 256 * 128) {
        int o = i >> 7, k = i & 127;
        float v = (o < 128) ? a[o * 384 + k] : a[(o - 128) * 384 + 128 + k];
        g_B1[i] = to_tf32(v);
    }
    if (i < 128 * 128) {
        int o = i >> 7, k = i & 127;
        g_B3[i] = to_tf32(a[o * 384 + 256 + k]);
    }
}

__device__ __forceinline__ float lrelu(float x) { return (x > 0.0f) ? x : 0.2f * x; }

// edge indices are int32 (JAX downcasts int64 without x64 enabled)
__device__ __forceinline__ void edge_src_dst(
    const int* __restrict__ edge, const int* __restrict__ nhop,
    int e, int E1, int E2, int& src, int& dst)
{
    if (e < E1) { src = edge[e]; dst = edge[E1 + e]; }
    else        { int e2 = e - E1; src = nhop[e2]; dst = nhop[E2 + e2]; }
}

__device__ __forceinline__ void mma_tf32(float* c, const uint32_t* a, const uint32_t* b) {
    asm volatile(
        "mma.sync.aligned.m16n8k8.row.col.f32.tf32.tf32.f32 "
        "{%0,%1,%2,%3}, {%4,%5,%6,%7}, {%8,%9}, {%0,%1,%2,%3};"
        : "+f"(c[0]), "+f"(c[1]), "+f"(c[2]), "+f"(c[3])
        : "r"(a[0]), "r"(a[1]), "r"(a[2]), "r"(a[3]), "r"(b[0]), "r"(b[1]));
}

// ---------------- tf32 tensor-core GEMM: C[m][n] = sum_k A[m][k]*B[n][k], K=128 ----------------
// Block tile 128M x 64N (blockIdx.y picks the 64-col slice), 8 warps (4M x 2N),
// warp tile 32x32 (2x4 m16n8k8 atoms) -> acc=32 regs -> 3 CTAs/SM.
// mode 0: B = g_B1 (256 N total, y=0..3), C = g_PQ ldc=256.
// mode 1: B = g_B3 (128 N, y=0..1), fused edge epilogue with global partial dot.
__global__ __launch_bounds__(256, 3) void k_sgemm(
    const float* __restrict__ A0, const float* __restrict__ A1, int splitM,
    int M, int mode,
    const int* __restrict__ edge, const int* __restrict__ nhop,
    const float* __restrict__ a2, int E1, int E2)
{
    __shared__ __align__(16) float As[32 * 132];   // A: 32 segs of 33 float4
    __shared__ __align__(16) float Bs[32 * 66];    // B: 32 segs of 33 float2
    __shared__ float a2s[64];

    const float* __restrict__ B =
        ((mode == 0) ? g_B1 : g_B3) + (size_t)(blockIdx.y * 64) * 128;

    const int t     = threadIdx.x;
    const int lane  = t & 31;
    const int wid   = t >> 5;
    const int warpM = wid >> 1;   // 0..3
    const int warpN = wid & 1;    // 0..1
    const int m0    = blockIdx.x * 128;
    const int n0w   = blockIdx.y * 64;

    if (mode == 1 && t < 64) a2s[t] = a2[n0w + t];

    float acc[2][4][4];
#pragma unroll
    for (int i = 0; i < 2; i++)
#pragma unroll
        for (int j = 0; j < 4; j++)
#pragma unroll
            for (int c = 0; c < 4; c++) acc[i][j][c] = 0.0f;

    const int srow = t >> 3;        // 0..31
    const int scol = (t & 7) * 4;   // 0,4,...,28

    const int i_s   = srow >> 4;
    const int lane0 = (srow & 7) << 2;
    const int ks_s  = scol >> 3;
    const int cA    = ((scol >> 2) & 1) * 2 + ((srow >> 3) & 1);
    const int eB    = (scol >> 2) & 1;

    float4 pa[4];
    auto loadA = [&](int kc) {
#pragma unroll
        for (int p = 0; p < 4; ++p) {
            int m = m0 + p * 32 + srow;
            float4 v = make_float4(0.f, 0.f, 0.f, 0.f);
            if (m < M) {
                const float* arow = (m < splitM) ? (A0 + (size_t)m * 128)
                                                 : (A1 + (size_t)(m - splitM) * 128);
                v = *reinterpret_cast<const float4*>(arow + kc + scol);
            }
            pa[p] = v;
        }
    };

    loadA(0);

    for (int kc = 0; kc < 128; kc += 32) {
        // ---- stage A (cvt to tf32) ----
#pragma unroll
        for (int p = 0; p < 4; ++p) {
            int segA = (p * 2 + i_s) * 4 + ks_s;
            float* ap = As + segA * 132 + lane0 * 4 + cA;
            ap[0]  = to_tf32(pa[p].x);
            ap[4]  = to_tf32(pa[p].y);
            ap[8]  = to_tf32(pa[p].z);
            ap[12] = to_tf32(pa[p].w);
        }
        // ---- stage B (already tf32; 64 rows = 2 row-blocks) ----
#pragma unroll
        for (int p = 0; p < 2; ++p) {
            int nn = p * 32 + srow;                   // 0..63 within slice
            float4 v = *reinterpret_cast<const float4*>(B + (size_t)nn * 128 + kc + scol);
            int segB = (nn >> 3) * 4 + ks_s;
            float* bp = Bs + segB * 66 + (nn & 7) * 8 + eB;
            bp[0] = v.x; bp[2] = v.y; bp[4] = v.z; bp[6] = v.w;
        }
        __syncthreads();

        if (kc < 96) loadA(kc + 32);   // prefetch; lands under MMAs

#pragma unroll
        for (int ks = 0; ks < 4; ++ks) {
            uint32_t af[2][4];
#pragma unroll
            for (int i = 0; i < 2; i++) {
                int seg = (warpM * 2 + i) * 4 + ks;
                float4 fa = reinterpret_cast<const float4*>(As + seg * 132)[lane];
                af[i][0] = __float_as_uint(fa.x);
                af[i][1] = __float_as_uint(fa.y);
                af[i][2] = __float_as_uint(fa.z);
                af[i][3] = __float_as_uint(fa.w);
            }
            uint32_t bf[4][2];
#pragma unroll
            for (int j = 0; j < 4; j++) {
                int seg = (warpN * 4 + j) * 4 + ks;
                float2 fb = reinterpret_cast<const float2*>(Bs + seg * 66)[lane];
                bf[j][0] = __float_as_uint(fb.x);
                bf[j][1] = __float_as_uint(fb.y);
            }
#pragma unroll
            for (int i = 0; i < 2; i++)
#pragma unroll
                for (int j = 0; j < 4; j++)
                    mma_tf32(acc[i][j], af[i], bf[j]);
        }
        __syncthreads();
    }

    if (mode == 0) {
#pragma unroll
        for (int i = 0; i < 2; i++) {
            int m = m0 + warpM * 32 + i * 16 + (lane >> 2);
#pragma unroll
            for (int j = 0; j < 4; j++) {
                int col = n0w + warpN * 32 + j * 8 + 2 * (lane & 3);
                if (m < M)
                    *reinterpret_cast<float2*>(&g_PQ[(size_t)m * 256 + col]) =
                        make_float2(acc[i][j][0], acc[i][j][1]);
                if (m + 8 < M)
                    *reinterpret_cast<float2*>(&g_PQ[(size_t)(m + 8) * 256 + col]) =
                        make_float2(acc[i][j][2], acc[i][j][3]);
            }
        }
        return;
    }

    // ---- fused edge epilogue (mode 1): partial dot over this block's 64 cols ----
#pragma unroll
    for (int i = 0; i < 2; i++) {
#pragma unroll
        for (int half = 0; half < 2; half++) {
            int rl = warpM * 32 + i * 16 + (lane >> 2) + 8 * half;
            int m = m0 + rl;
            float s = 0.0f;
            if (m < M) {
                int src, dst;
                edge_src_dst(edge, nhop, m, E1, E2, src, dst);
                const float* pbase = g_PQ + (size_t)src * 256;
                const float* qbase = g_PQ + (size_t)dst * 256 + 128;
                float* crow = g_edge_m + (size_t)m * 128;
#pragma unroll
                for (int j = 0; j < 4; j++) {
                    int lc  = warpN * 32 + j * 8 + 2 * (lane & 3);
                    int col = n0w + lc;
                    float c0 = acc[i][j][half * 2 + 0];
                    float c1 = acc[i][j][half * 2 + 1];
                    float2 pv = *reinterpret_cast<const float2*>(pbase + col);
                    float2 qv = *reinterpret_cast<const float2*>(qbase + col);
                    float v0 = lrelu(c0 + pv.x + qv.x);
                    float v1 = lrelu(c1 + pv.y + qv.y);
                    *reinterpret_cast<float2*>(crow + col) = make_float2(v0, v1);
                    s += v0 * a2s[lc] + v1 * a2s[lc + 1];
                }
            }
            s += __shfl_xor_sync(0xffffffffu, s, 1);
            s += __shfl_xor_sync(0xffffffffu, s, 2);
            if ((lane & 3) == 0 && m < M) atomicAdd(&g_sdot[m], s);
        }
    }
}

// ---------------- edge_e = exp(-lrelu(sdot)); a_rowsum ----------------
__global__ void k_edgee(const int* __restrict__ edge, const int* __restrict__ nhop,
                        int E1, int E2, int E)
{
    int e = blockIdx.x * blockDim.x + threadIdx.x;
    if (e >= E) return;
    int src, dst;
    edge_src_dst(edge, nhop, e, E1, E2, src, dst);
    float ee = expf(-lrelu(g_sdot[e]));
    g_edge_e[e] = ee;
    atomicAdd(&g_arow[dst], ee);
}

// ---------------- rel_att + e_rowsum ----------------
__global__ void k_rel(const int* __restrict__ edge, const int* __restrict__ nhop,
                      int E1, int E2, int E)
{
    int e = blockIdx.x * blockDim.x + threadIdx.x;
    if (e >= E) return;
    int src, dst;
    edge_src_dst(edge, nhop, e, E1, E2, src, dst);
    float as = g_arow[dst];
    if (as == 0.0f) as = 1e-12f;
    float r = g_edge_e[e] / as;
    g_rel_att[e] = r;
    atomicAdd(&g_erow[src], r);
}

// ---------------- val + e_colsum ----------------
__global__ void k_val(const int* __restrict__ edge, const int* __restrict__ nhop,
                      const float* __restrict__ entity_rank, int E1, int E2, int E)
{
    int e = blockIdx.x * blockDim.x + threadIdx.x;
    if (e >= E) return;
    int src, dst;
    edge_src_dst(edge, nhop, e, E1, E2, src, dst);
    float es = g_erow[src];
    if (es == 0.0f) es = 1e-12f;
    float v = g_rel_att[e] * entity_rank[src] / es;
    atomicAdd(&g_ecol[dst], v);
}

// ---------------- new_rank ----------------
__global__ void k_rank(float* __restrict__ out, int N, int out_size) {
    int n = blockIdx.x * blockDim.x + threadIdx.x;
    if (n >= N) return;
    float nr = 0.15f + 0.85f * g_ecol[n];
    g_new_rank[n] = nr;
    if (out_size >= N * 128 + N) out[(size_t)N * 128 + n] = nr;
}

// ---------------- scatter with vector RED ----------------
__global__ __launch_bounds__(128) void k_scatter(
    const int* __restrict__ edge, const int* __restrict__ nhop,
    float* __restrict__ out, int E1, int E2, int E)
{
    int e = blockIdx.x * 4 + (threadIdx.x >> 5);
    if (e >= E) return;
    int lane = threadIdx.x & 31;
    int src, dst;
    edge_src_dst(edge, nhop, e, E1, E2, src, dst);
    float w = g_rel_att[e] * g_new_rank[src];
    float4 v = *reinterpret_cast<const float4*>(&g_edge_m[(size_t)e * 128 + lane * 4]);
    float* p = out + (size_t)dst * 128 + lane * 4;
    asm volatile("red.global.add.v4.f32 [%0], {%1, %2, %3, %4};"
                 :: "l"(p), "f"(w * v.x), "f"(w * v.y), "f"(w * v.z), "f"(w * v.w)
                 : "memory");
}

// ---------------- ELU ----------------
__global__ void k_elu(float* __restrict__ out, int total) {
    int i = blockIdx.x * blockDim.x + threadIdx.x;
    if (i >= total) return;
    float x = out[i];
    out[i] = (x > 0.0f) ? x : expm1f(x);
}

// ---------------- launch ----------------
extern "C" void kernel_launch(void* const* d_in, const int* in_sizes, int n_in,
                              void* d_out, int out_size) {
    const float* input       = (const float*)d_in[0];
    const int*   edge        = (const int*)d_in[1];
    const float* edge_embed  = (const float*)d_in[2];
    const int*   edge_nhop   = (const int*)d_in[3];
    const float* embed_nhop  = (const float*)d_in[4];
    const float* entity_rank = (const float*)d_in[5];
    const float* a           = (const float*)d_in[6];
    const float* a2          = (const float*)d_in[7];
    float* out = (float*)d_out;

    int N  = in_sizes[0] / 128;
    int E1 = in_sizes[1] / 2;
    int E2 = in_sizes[3] / 2;
    int E  = E1 + E2;

    k_init<<<(N * 128 + 255) / 256, 256>>>(out, N, E);
    k_prep<<<(256 * 128 + 255) / 256, 256>>>(a);

    // P|Q for all nodes (N cols = 256 -> 4 slices)
    dim3 g_pq((N + 127) / 128, 4);
    k_sgemm<<<g_pq, 256>>>(input, input, N, N, 0, nullptr, nullptr, nullptr, 0, 0);

    // R = emb @ A3^T fused with edge_m / partial-dot epilogue (N = 128 -> 2 slices)
    dim3 g_r((E + 127) / 128, 2);
    k_sgemm<<<g_r, 256>>>(edge_embed, embed_nhop, E1, E, 1, edge, edge_nhop, a2, E1, E2);

    k_edgee<<<(E + 255) / 256, 256>>>(edge, edge_nhop, E1, E2, E);
    k_rel<<<(E + 255) / 256, 256>>>(edge, edge_nhop, E1, E2, E);
    k_val<<<(E + 255) / 256, 256>>>(edge, edge_nhop, entity_rank, E1, E2, E);
    k_rank<<<(N + 255) / 256, 256>>>(out, N, out_size);
    k_scatter<<<(E + 3) / 4, 128>>>(edge, edge_nhop, out, E1, E2, E);
    k_elu<<<(N * 128 + 255) / 256, 256>>>(out, N * 128);
}

// round 16
// speedup vs baseline: 1.6296x; 1.0187x over previous
#include <cuda_runtime.h>
#include <cstdint>
#include <cstddef>

#define N_MAX 50000
#define E_MAX 500000

// ---------------- scratch ----------------
__device__ float g_PQ[(size_t)N_MAX * 256];
__device__ float g_edge_m[(size_t)E_MAX * 128];
// pre-permuted tf32 B matrices (fragment-segment layout, see bperm)
__device__ float g_B1p[2 * 16384];   // two 128-col slices: y=0 -> A1 (P), y=1 -> A2 (Q)
__device__ float g_B3p[16384];
__device__ float g_edge_e[E_MAX];
__device__ float g_rel_att[E_MAX];
__device__ float g_arow[N_MAX];
__device__ float g_erow[N_MAX];
__device__ float g_ecol[N_MAX];
__device__ float g_new_rank[N_MAX];

__device__ __forceinline__ float to_tf32(float x) {
    uint32_t u;
    asm("cvt.rna.tf32.f32 %0, %1;" : "=r"(u) : "f"(x));
    return __uint_as_float(u);
}

// permuted index for B[nn][k], nn in [0,128), k in [0,128):
// chunk(k>>5) major, seg = (nn>>3)*4 + ((k&31)>>3) of 64 floats,
// float2 idx = (nn&7)*4 + (k&3), elem = (k>>2)&1
__device__ __forceinline__ int bperm(int nn, int k) {
    int kk = k & 31;
    int seg = (nn >> 3) * 4 + (kk >> 3);
    int f2  = (nn & 7) * 4 + (kk & 3);
    return (k >> 5) * 4096 + seg * 64 + f2 * 2 + ((kk >> 2) & 1);
}

// ---------------- init ----------------
__global__ void k_init(float* __restrict__ out, int N) {
    int i = blockIdx.x * blockDim.x + threadIdx.x;
    int total = N * 128;
    if (i < total) out[i] = 0.0f;
    if (i < N) { g_arow[i] = 0.0f; g_erow[i] = 0.0f; g_ecol[i] = 0.0f; }
}

// ---------------- weight extraction: tf32-round + permute ----------------
__global__ void k_prep(const float* __restrict__ a) {
    int i = blockIdx.x * blockDim.x + threadIdx.x;
    if (i < 256 * 128) {              // [A1; A2]
        int o = i >> 7, k = i & 127;
        float v = (o < 128) ? a[o * 384 + k] : a[(o - 128) * 384 + 128 + k];
        int half = o >> 7, nn = o & 127;
        g_B1p[half * 16384 + bperm(nn, k)] = to_tf32(v);
    }
    if (i < 128 * 128) {              // A3
        int o = i >> 7, k = i & 127;
        g_B3p[bperm(o, k)] = to_tf32(a[o * 384 + 256 + k]);
    }
}

__device__ __forceinline__ float lrelu(float x) { return (x > 0.0f) ? x : 0.2f * x; }

// edge indices are int32 (JAX downcasts int64 without x64 enabled)
__device__ __forceinline__ void edge_src_dst(
    const int* __restrict__ edge, const int* __restrict__ nhop,
    int e, int E1, int E2, int& src, int& dst)
{
    if (e < E1) { src = edge[e]; dst = edge[E1 + e]; }
    else        { int e2 = e - E1; src = nhop[e2]; dst = nhop[E2 + e2]; }
}

__device__ __forceinline__ void mma_tf32(float* c, const uint32_t* a, const uint32_t* b) {
    asm volatile(
        "mma.sync.aligned.m16n8k8.row.col.f32.tf32.tf32.f32 "
        "{%0,%1,%2,%3}, {%4,%5,%6,%7}, {%8,%9}, {%0,%1,%2,%3};"
        : "+f"(c[0]), "+f"(c[1]), "+f"(c[2]), "+f"(c[3])
        : "r"(a[0]), "r"(a[1]), "r"(a[2]), "r"(a[3]), "r"(b[0]), "r"(b[1]));
}

__device__ __forceinline__ uint32_t smem_u32(const void* p) {
    return (uint32_t)__cvta_generic_to_shared(p);
}

// smem (floats): As[2*2112] | Bs[2*4096] | a2s[128] | sdot[64]
#define SMEM_FLOATS (4224 + 8192 + 128 + 64)
#define SMEM_BYTES  (SMEM_FLOATS * 4)

// ---------------- tf32 tensor-core GEMM: C[m][n] = sum_k A[m][k]*B[n][k], K=128 ----------------
// Block tile 64M x 128N, 8 warps (2M x 4N), warp tile 32x32 (2x4 m16n8k8), acc=32 regs.
// B: cp.async from pre-permuted gmem (double-buffered). A: reg-prefetch + cvt + permuted STS.
// mode 0: B = g_B1p + y*16384, C = g_PQ (cols y*128..), grid.y in {0,1}.
// mode 1: B = g_B3p, fused edge epilogue (full 128-col dot in-block).
__global__ __launch_bounds__(256, 3) void k_sgemm(
    const float* __restrict__ A0, const float* __restrict__ A1, int splitM,
    int M, int mode,
    const int* __restrict__ edge, const int* __restrict__ nhop,
    const float* __restrict__ a2, int E1, int E2)
{
    extern __shared__ __align__(16) float smem[];
    float* As   = smem;            // 2 x 2112
    float* Bs   = smem + 4224;     // 2 x 4096
    float* a2s  = smem + 12416;    // 128
    float* sdot = smem + 12544;    // 64

    const float* __restrict__ Bp =
        (mode == 0) ? (g_B1p + blockIdx.y * 16384) : g_B3p;

    const int t     = threadIdx.x;
    const int lane  = t & 31;
    const int wid   = t >> 5;
    const int warpM = wid >> 2;   // 0..1
    const int warpN = wid & 3;    // 0..3
    const int m0    = blockIdx.x * 64;

    if (t < 64) sdot[t] = 0.0f;
    if (mode == 1 && t < 128) a2s[t] = a2[t];

    float acc[2][4][4];
#pragma unroll
    for (int i = 0; i < 2; i++)
#pragma unroll
        for (int j = 0; j < 4; j++)
#pragma unroll
            for (int c = 0; c < 4; c++) acc[i][j][c] = 0.0f;

    const int srow = t >> 3;        // 0..31
    const int scol = (t & 7) * 4;   // 0,4,...,28

    const int i_s   = srow >> 4;
    const int lane0 = (srow & 7) << 2;
    const int ks_s  = scol >> 3;
    const int cA    = ((scol >> 2) & 1) * 2 + ((srow >> 3) & 1);

    float4 pa[2];
    auto loadA = [&](int kc) {
#pragma unroll
        for (int p = 0; p < 2; ++p) {
            int m = m0 + p * 32 + srow;
            float4 v = make_float4(0.f, 0.f, 0.f, 0.f);
            if (m < M) {
                const float* arow = (m < splitM) ? (A0 + (size_t)m * 128)
                                                 : (A1 + (size_t)(m - splitM) * 128);
                v = *reinterpret_cast<const float4*>(arow + kc + scol);
            }
            pa[p] = v;
        }
    };
    auto stageA = [&](float* buf) {
#pragma unroll
        for (int p = 0; p < 2; ++p) {
            int segA = (p * 2 + i_s) * 4 + ks_s;
            float* ap = buf + segA * 132 + lane0 * 4 + cA;
            ap[0]  = to_tf32(pa[p].x);
            ap[4]  = to_tf32(pa[p].y);
            ap[8]  = to_tf32(pa[p].z);
            ap[12] = to_tf32(pa[p].w);
        }
    };
    auto cpB = [&](int ci, float* buf) {
        const float* src = Bp + ci * 4096;
#pragma unroll
        for (int p = 0; p < 4; ++p) {
            int idx = t + p * 256;
            asm volatile("cp.async.cg.shared.global [%0], [%1], 16;"
                         :: "r"(smem_u32(buf + idx * 4)), "l"(src + idx * 4));
        }
        asm volatile("cp.async.commit_group;");
    };

    // prologue
    cpB(0, Bs);
    loadA(0);

#pragma unroll
    for (int ci = 0; ci < 4; ++ci) {
        stageA(As + (ci & 1) * 2112);
        if (ci < 3) cpB(ci + 1, Bs + ((ci + 1) & 1) * 4096);
        if (ci < 3) asm volatile("cp.async.wait_group 1;" ::: "memory");
        else        asm volatile("cp.async.wait_group 0;" ::: "memory");
        __syncthreads();
        if (ci < 3) loadA((ci + 1) * 32);

        const float* Ac = As + (ci & 1) * 2112;
        const float* Bc = Bs + (ci & 1) * 4096;
#pragma unroll
        for (int ks = 0; ks < 4; ++ks) {
            uint32_t af[2][4];
#pragma unroll
            for (int i = 0; i < 2; i++) {
                int seg = (warpM * 2 + i) * 4 + ks;
                float4 fa = reinterpret_cast<const float4*>(Ac + seg * 132)[lane];
                af[i][0] = __float_as_uint(fa.x);
                af[i][1] = __float_as_uint(fa.y);
                af[i][2] = __float_as_uint(fa.z);
                af[i][3] = __float_as_uint(fa.w);
            }
            uint32_t bf[4][2];
#pragma unroll
            for (int j = 0; j < 4; j++) {
                int seg = (warpN * 4 + j) * 4 + ks;
                float2 fb = reinterpret_cast<const float2*>(Bc + seg * 64)[lane];
                bf[j][0] = __float_as_uint(fb.x);
                bf[j][1] = __float_as_uint(fb.y);
            }
#pragma unroll
            for (int i = 0; i < 2; i++)
#pragma unroll
                for (int j = 0; j < 4; j++)
                    mma_tf32(acc[i][j], af[i], bf[j]);
        }
        __syncthreads();
    }

    if (mode == 0) {
        int colb = blockIdx.y * 128;
#pragma unroll
        for (int i = 0; i < 2; i++) {
            int m = m0 + warpM * 32 + i * 16 + (lane >> 2);
#pragma unroll
            for (int j = 0; j < 4; j++) {
                int col = colb + warpN * 32 + j * 8 + 2 * (lane & 3);
                if (m < M)
                    *reinterpret_cast<float2*>(&g_PQ[(size_t)m * 256 + col]) =
                        make_float2(acc[i][j][0], acc[i][j][1]);
                if (m + 8 < M)
                    *reinterpret_cast<float2*>(&g_PQ[(size_t)(m + 8) * 256 + col]) =
                        make_float2(acc[i][j][2], acc[i][j][3]);
            }
        }
        return;
    }

    // ---- fused edge epilogue (mode 1): full 128-col rows, in-smem dot ----
#pragma unroll
    for (int i = 0; i < 2; i++) {
#pragma unroll
        for (int half = 0; half < 2; half++) {
            int rl = warpM * 32 + i * 16 + (lane >> 2) + 8 * half;
            int m = m0 + rl;
            float s = 0.0f;
            if (m < M) {
                int src, dst;
                edge_src_dst(edge, nhop, m, E1, E2, src, dst);
                const float* pbase = g_PQ + (size_t)src * 256;
                const float* qbase = g_PQ + (size_t)dst * 256 + 128;
                float* crow = g_edge_m + (size_t)m * 128;
#pragma unroll
                for (int j = 0; j < 4; j++) {
                    int col = warpN * 32 + j * 8 + 2 * (lane & 3);
                    float c0 = acc[i][j][half * 2 + 0];
                    float c1 = acc[i][j][half * 2 + 1];
                    float2 pv = *reinterpret_cast<const float2*>(pbase + col);
                    float2 qv = *reinterpret_cast<const float2*>(qbase + col);
                    float v0 = lrelu(c0 + pv.x + qv.x);
                    float v1 = lrelu(c1 + pv.y + qv.y);
                    *reinterpret_cast<float2*>(crow + col) = make_float2(v0, v1);
                    s += v0 * a2s[col] + v1 * a2s[col + 1];
                }
            }
            s += __shfl_xor_sync(0xffffffffu, s, 1);
            s += __shfl_xor_sync(0xffffffffu, s, 2);
            if ((lane & 3) == 0 && m < M) atomicAdd(&sdot[rl], s);
        }
    }
    __syncthreads();
    if (t < 64) {
        int m = m0 + t;
        if (m < M) {
            int src, dst;
            edge_src_dst(edge, nhop, m, E1, E2, src, dst);
            float ee = expf(-lrelu(sdot[t]));
            g_edge_e[m] = ee;
            atomicAdd(&g_arow[dst], ee);
        }
    }
}

// ---------------- rel_att + e_rowsum ----------------
__global__ void k_rel(const int* __restrict__ edge, const int* __restrict__ nhop,
                      int E1, int E2, int E)
{
    int e = blockIdx.x * blockDim.x + threadIdx.x;
    if (e >= E) return;
    int src, dst;
    edge_src_dst(edge, nhop, e, E1, E2, src, dst);
    float as = g_arow[dst];
    if (as == 0.0f) as = 1e-12f;
    float r = g_edge_e[e] / as;
    g_rel_att[e] = r;
    atomicAdd(&g_erow[src], r);
}

// ---------------- val + e_colsum ----------------
__global__ void k_val(const int* __restrict__ edge, const int* __restrict__ nhop,
                      const float* __restrict__ entity_rank, int E1, int E2, int E)
{
    int e = blockIdx.x * blockDim.x + threadIdx.x;
    if (e >= E) return;
    int src, dst;
    edge_src_dst(edge, nhop, e, E1, E2, src, dst);
    float es = g_erow[src];
    if (es == 0.0f) es = 1e-12f;
    float v = g_rel_att[e] * entity_rank[src] / es;
    atomicAdd(&g_ecol[dst], v);
}

// ---------------- new_rank ----------------
__global__ void k_rank(float* __restrict__ out, int N, int out_size) {
    int n = blockIdx.x * blockDim.x + threadIdx.x;
    if (n >= N) return;
    float nr = 0.15f + 0.85f * g_ecol[n];
    g_new_rank[n] = nr;
    if (out_size >= N * 128 + N) out[(size_t)N * 128 + n] = nr;
}

// ---------------- scatter with vector RED ----------------
__global__ __launch_bounds__(128) void k_scatter(
    const int* __restrict__ edge, const int* __restrict__ nhop,
    float* __restrict__ out, int E1, int E2, int E)
{
    int e = blockIdx.x * 4 + (threadIdx.x >> 5);
    if (e >= E) return;
    int lane = threadIdx.x & 31;
    int src, dst;
    edge_src_dst(edge, nhop, e, E1, E2, src, dst);
    float w = g_rel_att[e] * g_new_rank[src];
    float4 v = *reinterpret_cast<const float4*>(&g_edge_m[(size_t)e * 128 + lane * 4]);
    float* p = out + (size_t)dst * 128 + lane * 4;
    asm volatile("red.global.add.v4.f32 [%0], {%1, %2, %3, %4};"
                 :: "l"(p), "f"(w * v.x), "f"(w * v.y), "f"(w * v.z), "f"(w * v.w)
                 : "memory");
}

// ---------------- ELU ----------------
__global__ void k_elu(float* __restrict__ out, int total) {
    int i = blockIdx.x * blockDim.x + threadIdx.x;
    if (i >= total) return;
    float x = out[i];
    out[i] = (x > 0.0f) ? x : expm1f(x);
}

// ---------------- launch ----------------
extern "C" void kernel_launch(void* const* d_in, const int* in_sizes, int n_in,
                              void* d_out, int out_size) {
    const float* input       = (const float*)d_in[0];
    const int*   edge        = (const int*)d_in[1];
    const float* edge_embed  = (const float*)d_in[2];
    const int*   edge_nhop   = (const int*)d_in[3];
    const float* embed_nhop  = (const float*)d_in[4];
    const float* entity_rank = (const float*)d_in[5];
    const float* a           = (const float*)d_in[6];
    const float* a2          = (const float*)d_in[7];
    float* out = (float*)d_out;

    int N  = in_sizes[0] / 128;
    int E1 = in_sizes[1] / 2;
    int E2 = in_sizes[3] / 2;
    int E  = E1 + E2;

    cudaFuncSetAttribute(k_sgemm, cudaFuncAttributeMaxDynamicSharedMemorySize, SMEM_BYTES);

    k_init<<<(N * 128 + 255) / 256, 256>>>(out, N);
    k_prep<<<(256 * 128 + 255) / 256, 256>>>(a);

    // P (y=0) and Q (y=1): C cols y*128..y*128+127
    dim3 g_pq((N + 63) / 64, 2);
    k_sgemm<<<g_pq, 256, SMEM_BYTES>>>(input, input, N, N, 0, nullptr, nullptr, nullptr, 0, 0);

    // R = emb @ A3^T fused with edge_m/edge_e/a_rowsum epilogue
    dim3 g_r((E + 63) / 64, 1);
    k_sgemm<<<g_r, 256, SMEM_BYTES>>>(edge_embed, embed_nhop, E1, E, 1, edge, edge_nhop, a2, E1, E2);

    k_rel<<<(E + 255) / 256, 256>>>(edge, edge_nhop, E1, E2, E);
    k_val<<<(E + 255) / 256, 256>>>(edge, edge_nhop, entity_rank, E1, E2, E);
    k_rank<<<(N + 255) / 256, 256>>>(out, N, out_size);
    k_scatter<<<(E + 3) / 4, 128>>>(edge, edge_nhop, out, E1, E2, E);
    k_elu<<<(N * 128 + 255) / 256, 256>>>(out, N * 128);
}